// round 12
// baseline (speedup 1.0000x reference)
#include <cuda_runtime.h>
#include <math.h>

#define N_ROWS 65536
#define NBLK   64
#define NTHR   256
#define NLB    1024       // local buckets per block (total 65536 global buckets)
#define CAP    1536       // smem element slots (mean 1024, sd ~32 -> 16 sigma)

typedef unsigned long long ull;

// ---------------- scratch (device globals; zero-init at load; kernel leaves
// g_bar/g_done zeroed for the next call) -------------------------------------
__device__ float    g_e2[N_ROWS], g_e3[N_ROWS];
__device__ double   g_csum2[NBLK], g_csum3[NBLK], g_part[NBLK];
__device__ unsigned g_bar[2];
__device__ unsigned g_done;

__device__ __forceinline__ unsigned bucket_of(float k) {
    k = fminf(fmaxf(k, 0.0f), 0.999999f);
    unsigned b = (unsigned)(k * 65536.0f);
    return b > 65535u ? 65535u : b;
}

// Grid barrier across NBLK blocks (single wave: 64 blocks on 148 SMs).
__device__ __forceinline__ void gbar(int i) {
    __syncthreads();
    if (threadIdx.x == 0) {
        __threadfence();
        atomicAdd(&g_bar[i], 1u);
        while (((volatile unsigned*)g_bar)[i] < NBLK) { }
        __threadfence();
    }
    __syncthreads();
}

// ===========================================================================
// K1: per-row cos-sim -> exp(e2,e3). 8192 blocks x 256 (1 warp/row).
// DRAM-bandwidth bound. No histogram anymore.
// ===========================================================================
__global__ void __launch_bounds__(256)
k1_main(const float4* __restrict__ x,
        const float4* __restrict__ o2,
        const float4* __restrict__ o3) {
    __shared__ float4 so2[128], so3[128];
    __shared__ float  red[8];
    __shared__ float  s_n2, s_n3;
    int t = threadIdx.x;
    if (t < 128)      so2[t]       = o2[t];
    else              so3[t - 128] = o3[t - 128];
    __syncthreads();

    float a;
    if (t < 128) { float4 v = so2[t];       a = v.x*v.x + v.y*v.y + v.z*v.z + v.w*v.w; }
    else         { float4 v = so3[t - 128]; a = v.x*v.x + v.y*v.y + v.z*v.z + v.w*v.w; }
#pragma unroll
    for (int o = 16; o > 0; o >>= 1) a += __shfl_xor_sync(0xFFFFFFFFu, a, o);
    int warp = t >> 5, lane = t & 31;
    if (lane == 0) red[warp] = a;
    __syncthreads();
    if (t == 0) {
        s_n2 = sqrtf(red[0] + red[1] + red[2] + red[3]);
        s_n3 = sqrtf(red[4] + red[5] + red[6] + red[7]);
    }
    __syncthreads();
    float n2 = s_n2, n3 = s_n3;

    int row = blockIdx.x * 8 + warp;
    const float4* xr = x + (size_t)row * 128;
    float d2 = 0.f, d3 = 0.f, nn = 0.f;
#pragma unroll
    for (int k = 0; k < 4; k++) {
        float4 v = xr[lane + 32 * k];
        float4 p = so2[lane + 32 * k];
        float4 q = so3[lane + 32 * k];
        d2 += v.x * p.x + v.y * p.y + v.z * p.z + v.w * p.w;
        d3 += v.x * q.x + v.y * q.y + v.z * q.z + v.w * q.w;
        nn += v.x * v.x + v.y * v.y + v.z * v.z + v.w * v.w;
    }
#pragma unroll
    for (int o = 16; o > 0; o >>= 1) {
        d2 += __shfl_xor_sync(0xFFFFFFFFu, d2, o);
        d3 += __shfl_xor_sync(0xFFFFFFFFu, d3, o);
        nn += __shfl_xor_sync(0xFFFFFFFFu, nn, o);
    }
    if (lane == 0) {
        float nx = sqrtf(nn);
        g_e2[row] = expf(d2 / fmaxf(nx * n2, 1e-8f));
        g_e3[row] = expf(d3 / fmaxf(nx * n3, 1e-8f));
    }
}

// ===========================================================================
// K2: each block owns key range [blk/64,(blk+1)/64). Scans ALL keys, local
// sort entirely in smem, ONE grid barrier, local prefix+logs, finish.
// 64 blocks x 256 threads.
// ===========================================================================
__global__ void __launch_bounds__(256)
k2_fused(const float* __restrict__ rank, float* __restrict__ out) {
    __shared__ union {
        ull list[CAP];                                 // phases 1-3
        struct { float e2[CAP]; float e3[CAP]; } e;    // phase 5+
    } uA;
    __shared__ ull      s_sorted[CAP];
    __shared__ unsigned s_lhist[NLB];                  // histogram, then counters
    __shared__ unsigned s_lofs[NLB];
    __shared__ unsigned s_nloc;
    __shared__ unsigned s_wtu[8];
    __shared__ double   s_wt2[8], s_wt3[8];
    __shared__ double   s_c2[NBLK], s_c3[NBLK];
    __shared__ bool     amLast;

    int t = threadIdx.x, blk = blockIdx.x;
    int warp = t >> 5, lane = t & 31;

    for (int j = t; j < NLB; j += NTHR) s_lhist[j] = 0u;
    if (t == 0) s_nloc = 0u;
    __syncthreads();

    // ---- Phase 1: scan all 65536 keys, keep ours ---------------------------
    const float4* r4 = (const float4*)rank;
#pragma unroll 4
    for (int r = 0; r < 64; r++) {
        int vi = t + NTHR * r;
        float4 kv = r4[vi];
        int bi = vi * 4;
        float kk[4] = {kv.x, kv.y, kv.z, kv.w};
#pragma unroll
        for (int j = 0; j < 4; j++) {
            unsigned g = bucket_of(kk[j]);
            if ((g >> 10) == (unsigned)blk) {
                unsigned p = atomicAdd(&s_nloc, 1u);
                if (p < CAP) {
                    uA.list[p] = ((ull)__float_as_uint(kk[j]) << 32) | (unsigned)(bi + j);
                    atomicAdd(&s_lhist[g & 1023u], 1u);
                }
            }
        }
    }
    __syncthreads();
    unsigned n_loc = s_nloc;
    if (n_loc > CAP) n_loc = CAP;                       // 16-sigma safety clamp

    // ---- Phase 2: block exclusive scan of 1024 local bins ------------------
    unsigned b0 = t * 4;
    unsigned h[4], ofs[4];
#pragma unroll
    for (int j = 0; j < 4; j++) h[j] = s_lhist[b0 + j];
    unsigned hs = h[0] + h[1] + h[2] + h[3];
    unsigned v = hs;
#pragma unroll
    for (int o = 1; o < 32; o <<= 1) {
        unsigned u = __shfl_up_sync(0xFFFFFFFFu, v, o);
        if (lane >= o) v += u;
    }
    if (lane == 31) s_wtu[warp] = v;
    __syncthreads();
    if (t < 8) {
        unsigned x = s_wtu[t];
#pragma unroll
        for (int o = 1; o < 8; o <<= 1) {
            unsigned u = __shfl_up_sync(0xFFu, x, o);
            if (t >= o) x += u;
        }
        s_wtu[t] = x;
    }
    __syncthreads();
    unsigned exth = v + (warp ? s_wtu[warp - 1] : 0u) - hs;
    ofs[0] = exth;
    ofs[1] = ofs[0] + h[0];
    ofs[2] = ofs[1] + h[1];
    ofs[3] = ofs[2] + h[2];
#pragma unroll
    for (int j = 0; j < 4; j++) { s_lofs[b0 + j] = ofs[j]; s_lhist[b0 + j] = 0u; }
    __syncthreads();

    // ---- Phase 3: smem scatter into bucket slots ---------------------------
    for (unsigned i = t; i < n_loc; i += NTHR) {
        ull e = uA.list[i];
        unsigned g = bucket_of(__uint_as_float((unsigned)(e >> 32))) & 1023u;
        unsigned slot = s_lofs[g] + atomicAdd(&s_lhist[g], 1u);
        s_sorted[slot] = e;
    }
    __syncthreads();

    // ---- Phase 4: in-bucket selection sort (u64 total order, deterministic)
#pragma unroll
    for (int j = 0; j < 4; j++) {
        unsigned hh = h[j];
        if (hh >= 2u) {
            unsigned base = ofs[j];
            for (unsigned p = 0; p + 1 < hh; p++) {
                unsigned m = p;
                for (unsigned q = p + 1; q < hh; q++)
                    if (s_sorted[base + q] < s_sorted[base + m]) m = q;
                if (m != p) {
                    ull tmp = s_sorted[base + p];
                    s_sorted[base + p] = s_sorted[base + m];
                    s_sorted[base + m] = tmp;
                }
            }
        }
    }
    __syncthreads();

    // ---- Phase 5: gather e2/e3 (L2), local sums ----------------------------
    double sum2 = 0.0, sum3 = 0.0;
    for (unsigned i = t; i < n_loc; i += NTHR) {
        unsigned idx = (unsigned)(s_sorted[i] & 0xFFFFFFFFu);
        float e2v = g_e2[idx], e3v = g_e3[idx];
        uA.e.e2[i] = e2v; uA.e.e3[i] = e3v;
        sum2 += e2v; sum3 += e3v;
    }
    {
        double a2 = sum2, a3 = sum3;
#pragma unroll
        for (int o = 16; o > 0; o >>= 1) {
            a2 += __shfl_xor_sync(0xFFFFFFFFu, a2, o);
            a3 += __shfl_xor_sync(0xFFFFFFFFu, a3, o);
        }
        if (lane == 0) { s_wt2[warp] = a2; s_wt3[warp] = a3; }
        __syncthreads();
        if (t == 0) {
            double c2 = 0.0, c3 = 0.0;
            for (int j = 0; j < 8; j++) { c2 += s_wt2[j]; c3 += s_wt3[j]; }
            g_csum2[blk] = c2; g_csum3[blk] = c3;
        }
    }
    gbar(0);                                            // THE one grid barrier

    // ---- Phase 6: redundant 64-scan of block sums; prefix + logs -----------
    if (t < NBLK) { s_c2[t] = __ldcg(&g_csum2[t]); s_c3[t] = __ldcg(&g_csum3[t]); }
    __syncthreads();
#pragma unroll
    for (int o = 1; o < NBLK; o <<= 1) {
        double u2 = (t >= o && t < NBLK) ? s_c2[t - o] : 0.0;
        double u3 = (t >= o && t < NBLK) ? s_c3[t - o] : 0.0;
        __syncthreads();
        if (t < NBLK) { s_c2[t] += u2; s_c3[t] += u3; }
        __syncthreads();
    }
    double tot2 = s_c2[NBLK - 1], tot3 = s_c3[NBLK - 1];
    double carry2 = (blk > 0) ? s_c2[blk - 1] : 0.0;
    double carry3 = (blk > 0) ? s_c3[blk - 1] : 0.0;

    double ls = 0.0;
    int R = (int)((n_loc + NTHR - 1) / NTHR);
    for (int r = 0; r < R; r++) {
        int i = r * NTHR + t;
        bool valid = i < (int)n_loc;
        double v2 = valid ? (double)uA.e.e2[i] : 0.0;
        double v3 = valid ? (double)uA.e.e3[i] : 0.0;
#pragma unroll
        for (int o = 1; o < 32; o <<= 1) {
            double u2 = __shfl_up_sync(0xFFFFFFFFu, v2, o);
            double u3 = __shfl_up_sync(0xFFFFFFFFu, v3, o);
            if (lane >= o) { v2 += u2; v3 += u3; }
        }
        if (lane == 31) { s_wt2[warp] = v2; s_wt3[warp] = v3; }
        __syncthreads();
        if (t < 8) {
            double x2 = s_wt2[t], x3 = s_wt3[t];
#pragma unroll
            for (int o = 1; o < 8; o <<= 1) {
                double u2 = __shfl_up_sync(0xFFu, x2, o);
                double u3 = __shfl_up_sync(0xFFu, x3, o);
                if (t >= o) { x2 += u2; x3 += u3; }
            }
            s_wt2[t] = x2; s_wt3[t] = x3;
        }
        __syncthreads();
        if (valid) {
            double incl2 = v2 + (warp ? s_wt2[warp - 1] : 0.0);
            double incl3 = v3 + (warp ? s_wt3[warp - 1] : 0.0);
            ls += (double)logf((float)(carry2 + incl2)) +
                  (double)logf((float)(carry3 + incl3));
        }
        carry2 += s_wt2[7];
        carry3 += s_wt3[7];
        __syncthreads();
    }

#pragma unroll
    for (int o = 16; o > 0; o >>= 1) ls += __shfl_xor_sync(0xFFFFFFFFu, ls, o);
    if (lane == 0) s_wt2[warp] = ls;
    __syncthreads();
    if (t == 0) {
        double s = 0.0;
        for (int j = 0; j < 8; j++) s += s_wt2[j];
        g_part[blk] = s;
    }

    // ---- Final: last block reduces partials, writes out, resets state ------
    if (t == 0) {
        __threadfence();
        amLast = (atomicAdd(&g_done, 1u) == NBLK - 1);
    }
    __syncthreads();
    if (amLast) {
        double p = (t < NBLK) ? __ldcg(&g_part[t]) : 0.0;
#pragma unroll
        for (int o = 16; o > 0; o >>= 1) p += __shfl_xor_sync(0xFFFFFFFFu, p, o);
        __syncthreads();
        if (lane == 0) s_wt2[warp] = p;
        __syncthreads();
        if (t == 0) {
            double s = 0.0;
            for (int j = 0; j < 8; j++) s += s_wt2[j];
            out[0] = (float)((double)N_ROWS * (log(tot2) + log(tot3)) - s);
            g_done = 0u;                                 // all blocks counted; safe
            g_bar[0] = 0u;                               // all blocks past gbar; safe
        }
    }
}

extern "C" void kernel_launch(void* const* d_in, const int* in_sizes, int n_in,
                              void* d_out, int out_size) {
    const float* o1   = (const float*)d_in[0];  // [65536, 512]
    const float* o2   = (const float*)d_in[1];  // [1, 512]
    const float* o3   = (const float*)d_in[2];  // [1, 512]
    const float* rank = (const float*)d_in[3];  // [65536]
    float* out = (float*)d_out;

    k1_main<<<N_ROWS / 8, 256>>>((const float4*)o1, (const float4*)o2,
                                 (const float4*)o3);
    k2_fused<<<NBLK, NTHR>>>(rank, out);
}

// round 13
// speedup vs baseline: 1.1556x; 1.1556x over previous
#include <cuda_runtime.h>
#include <math.h>

#define N_ROWS 65536
#define NBLK   64
#define NTHR   256
#define NLB    1024       // local buckets per owner block (64*1024 = 65536 global)
#define CAP    1536       // slots per box (mean 1024, sd ~32 -> 16 sigma)

typedef unsigned long long ull;

// ---------------- scratch (zero-init at load; kernel re-zeroes its state) ---
__device__ float    g_e2[N_ROWS], g_e3[N_ROWS];
__device__ ull      g_box[NBLK * CAP];              // per-owner-block FIFOs
__device__ unsigned g_boxcnt[NBLK];
__device__ double   g_csum2[NBLK], g_csum3[NBLK], g_part[NBLK];
__device__ unsigned g_bar[2];
__device__ unsigned g_done;

__device__ __forceinline__ unsigned bucket_of(float k) {
    k = fminf(fmaxf(k, 0.0f), 0.999999f);
    unsigned b = (unsigned)(k * 65536.0f);
    return b > 65535u ? 65535u : b;
}

__device__ __forceinline__ void gbar(int i) {
    __syncthreads();
    if (threadIdx.x == 0) {
        __threadfence();
        atomicAdd(&g_bar[i], 1u);
        while (((volatile unsigned*)g_bar)[i] < NBLK) { }
        __threadfence();
    }
    __syncthreads();
}

// ===========================================================================
// K1: per-row cos-sim -> exp. 2 rows per warp (8 outstanding float4 loads).
// 4096 blocks x 256 threads. DRAM-bandwidth bound.
// ===========================================================================
__global__ void __launch_bounds__(256)
k1_main(const float4* __restrict__ x,
        const float4* __restrict__ o2,
        const float4* __restrict__ o3) {
    __shared__ float4 so2[128], so3[128];
    __shared__ float  red[8];
    __shared__ float  s_n2, s_n3;
    int t = threadIdx.x;
    if (t < 128)      so2[t]       = o2[t];
    else              so3[t - 128] = o3[t - 128];
    __syncthreads();

    float a;
    if (t < 128) { float4 v = so2[t];       a = v.x*v.x + v.y*v.y + v.z*v.z + v.w*v.w; }
    else         { float4 v = so3[t - 128]; a = v.x*v.x + v.y*v.y + v.z*v.z + v.w*v.w; }
#pragma unroll
    for (int o = 16; o > 0; o >>= 1) a += __shfl_xor_sync(0xFFFFFFFFu, a, o);
    int warp = t >> 5, lane = t & 31;
    if (lane == 0) red[warp] = a;
    __syncthreads();
    if (t == 0) {
        s_n2 = sqrtf(red[0] + red[1] + red[2] + red[3]);
        s_n3 = sqrtf(red[4] + red[5] + red[6] + red[7]);
    }
    __syncthreads();
    float n2 = s_n2, n3 = s_n3;

    int row0 = blockIdx.x * 16 + warp * 2;
    const float4* xa = x + (size_t)row0 * 128;
    const float4* xb = xa + 128;

    float d2a = 0.f, d3a = 0.f, nna = 0.f;
    float d2b = 0.f, d3b = 0.f, nnb = 0.f;
#pragma unroll
    for (int k = 0; k < 4; k++) {
        float4 va = xa[lane + 32 * k];
        float4 vb = xb[lane + 32 * k];
        float4 p  = so2[lane + 32 * k];
        float4 q  = so3[lane + 32 * k];
        d2a += va.x*p.x + va.y*p.y + va.z*p.z + va.w*p.w;
        d3a += va.x*q.x + va.y*q.y + va.z*q.z + va.w*q.w;
        nna += va.x*va.x + va.y*va.y + va.z*va.z + va.w*va.w;
        d2b += vb.x*p.x + vb.y*p.y + vb.z*p.z + vb.w*p.w;
        d3b += vb.x*q.x + vb.y*q.y + vb.z*q.z + vb.w*q.w;
        nnb += vb.x*vb.x + vb.y*vb.y + vb.z*vb.z + vb.w*vb.w;
    }
#pragma unroll
    for (int o = 16; o > 0; o >>= 1) {
        d2a += __shfl_xor_sync(0xFFFFFFFFu, d2a, o);
        d3a += __shfl_xor_sync(0xFFFFFFFFu, d3a, o);
        nna += __shfl_xor_sync(0xFFFFFFFFu, nna, o);
        d2b += __shfl_xor_sync(0xFFFFFFFFu, d2b, o);
        d3b += __shfl_xor_sync(0xFFFFFFFFu, d3b, o);
        nnb += __shfl_xor_sync(0xFFFFFFFFu, nnb, o);
    }
    if (lane == 0) {
        float nxa = sqrtf(nna), nxb = sqrtf(nnb);
        g_e2[row0]     = expf(d2a / fmaxf(nxa * n2, 1e-8f));
        g_e3[row0]     = expf(d3a / fmaxf(nxa * n3, 1e-8f));
        g_e2[row0 + 1] = expf(d2b / fmaxf(nxb * n2, 1e-8f));
        g_e3[row0 + 1] = expf(d3b / fmaxf(nxb * n3, 1e-8f));
    }
}

// ===========================================================================
// K2 (fused, 64 x 256): distributed route-to-owner -> gbar -> local smem sort
// -> gather+sums -> gbar -> prefix+logs -> finish. 2 grid barriers.
// ===========================================================================
__global__ void __launch_bounds__(256)
k2_fused(const float* __restrict__ rank, float* __restrict__ out) {
    __shared__ union {
        ull list[CAP];
        struct { float e2[CAP]; float e3[CAP]; } e;
    } uA;
    __shared__ ull      s_sorted[CAP];
    __shared__ unsigned s_bh[NBLK], s_bofs[NBLK], s_bcnt[NBLK];
    __shared__ unsigned s_lhist[NLB], s_lofs[NLB];
    __shared__ unsigned s_wtu[8];
    __shared__ double   s_wt2[8], s_wt3[8];
    __shared__ double   s_c2[NBLK], s_c3[NBLK];
    __shared__ bool     amLast;

    int t = threadIdx.x, blk = blockIdx.x;
    int warp = t >> 5, lane = t & 31;

    // ---- Phase A: route my 1024 contiguous keys to owner boxes -------------
    if (t < NBLK) { s_bh[t] = 0u; s_bcnt[t] = 0u; }
    __syncthreads();
    int i0 = blk * 1024 + t * 4;
    float4 kv = *(const float4*)&rank[i0];
    float kk[4] = {kv.x, kv.y, kv.z, kv.w};
    unsigned gb[4];
#pragma unroll
    for (int j = 0; j < 4; j++) {
        gb[j] = bucket_of(kk[j]);
        atomicAdd(&s_bh[gb[j] >> 10], 1u);
    }
    __syncthreads();
    if (t < NBLK && s_bh[t] != 0u)
        s_bofs[t] = atomicAdd(&g_boxcnt[t], s_bh[t]);
    __syncthreads();
#pragma unroll
    for (int j = 0; j < 4; j++) {
        unsigned box = gb[j] >> 10;
        unsigned pos = s_bofs[box] + atomicAdd(&s_bcnt[box], 1u);
        if (pos < CAP)
            g_box[box * CAP + pos] =
                ((ull)__float_as_uint(kk[j]) << 32) | (unsigned)(i0 + j);
    }
    gbar(0);

    // ---- Phase B: load my box; local bucket sort in smem -------------------
    unsigned n_loc = __ldcg(&g_boxcnt[blk]);
    if (n_loc > CAP) n_loc = CAP;

    for (int j = t; j < NLB; j += NTHR) s_lhist[j] = 0u;
    __syncthreads();
    for (unsigned i = t; i < n_loc; i += NTHR) {
        ull e = __ldcg(&g_box[blk * CAP + i]);
        uA.list[i] = e;
        unsigned g = bucket_of(__uint_as_float((unsigned)(e >> 32))) & 1023u;
        atomicAdd(&s_lhist[g], 1u);
    }
    __syncthreads();

    // block exclusive scan of 1024 local bins (4 per thread)
    unsigned b0 = t * 4;
    unsigned h[4], ofs[4];
#pragma unroll
    for (int j = 0; j < 4; j++) h[j] = s_lhist[b0 + j];
    unsigned hs = h[0] + h[1] + h[2] + h[3];
    unsigned v = hs;
#pragma unroll
    for (int o = 1; o < 32; o <<= 1) {
        unsigned u = __shfl_up_sync(0xFFFFFFFFu, v, o);
        if (lane >= o) v += u;
    }
    if (lane == 31) s_wtu[warp] = v;
    __syncthreads();
    if (t < 8) {
        unsigned x = s_wtu[t];
#pragma unroll
        for (int o = 1; o < 8; o <<= 1) {
            unsigned u = __shfl_up_sync(0xFFu, x, o);
            if (t >= o) x += u;
        }
        s_wtu[t] = x;
    }
    __syncthreads();
    unsigned exth = v + (warp ? s_wtu[warp - 1] : 0u) - hs;
    ofs[0] = exth;
    ofs[1] = ofs[0] + h[0];
    ofs[2] = ofs[1] + h[1];
    ofs[3] = ofs[2] + h[2];
#pragma unroll
    for (int j = 0; j < 4; j++) { s_lofs[b0 + j] = ofs[j]; s_lhist[b0 + j] = 0u; }
    __syncthreads();

    // smem scatter into bucket slots
    for (unsigned i = t; i < n_loc; i += NTHR) {
        ull e = uA.list[i];
        unsigned g = bucket_of(__uint_as_float((unsigned)(e >> 32))) & 1023u;
        unsigned slot = s_lofs[g] + atomicAdd(&s_lhist[g], 1u);
        s_sorted[slot] = e;
    }
    __syncthreads();

    // in-bucket selection sort (u64 total order -> deterministic)
#pragma unroll
    for (int j = 0; j < 4; j++) {
        unsigned hh = h[j];
        if (hh >= 2u) {
            unsigned base = ofs[j];
            for (unsigned p = 0; p + 1 < hh; p++) {
                unsigned m = p;
                for (unsigned q = p + 1; q < hh; q++)
                    if (s_sorted[base + q] < s_sorted[base + m]) m = q;
                if (m != p) {
                    ull tmp = s_sorted[base + p];
                    s_sorted[base + p] = s_sorted[base + m];
                    s_sorted[base + m] = tmp;
                }
            }
        }
    }
    __syncthreads();

    // ---- Phase C: gather e2/e3 (L2), local sums ----------------------------
    double sum2 = 0.0, sum3 = 0.0;
    for (unsigned i = t; i < n_loc; i += NTHR) {
        unsigned idx = (unsigned)(s_sorted[i] & 0xFFFFFFFFu);
        float e2v = g_e2[idx], e3v = g_e3[idx];
        uA.e.e2[i] = e2v; uA.e.e3[i] = e3v;
        sum2 += e2v; sum3 += e3v;
    }
    {
        double a2 = sum2, a3 = sum3;
#pragma unroll
        for (int o = 16; o > 0; o >>= 1) {
            a2 += __shfl_xor_sync(0xFFFFFFFFu, a2, o);
            a3 += __shfl_xor_sync(0xFFFFFFFFu, a3, o);
        }
        if (lane == 0) { s_wt2[warp] = a2; s_wt3[warp] = a3; }
        __syncthreads();
        if (t == 0) {
            double c2 = 0.0, c3 = 0.0;
            for (int j = 0; j < 8; j++) { c2 += s_wt2[j]; c3 += s_wt3[j]; }
            g_csum2[blk] = c2; g_csum3[blk] = c3;
        }
    }
    gbar(1);

    // ---- Phase D: 64-scan of block sums (redundant); prefix + logs ---------
    if (t < NBLK) { s_c2[t] = __ldcg(&g_csum2[t]); s_c3[t] = __ldcg(&g_csum3[t]); }
    __syncthreads();
#pragma unroll
    for (int o = 1; o < NBLK; o <<= 1) {
        double u2 = (t >= o && t < NBLK) ? s_c2[t - o] : 0.0;
        double u3 = (t >= o && t < NBLK) ? s_c3[t - o] : 0.0;
        __syncthreads();
        if (t < NBLK) { s_c2[t] += u2; s_c3[t] += u3; }
        __syncthreads();
    }
    double tot2 = s_c2[NBLK - 1], tot3 = s_c3[NBLK - 1];
    double carry2 = (blk > 0) ? s_c2[blk - 1] : 0.0;
    double carry3 = (blk > 0) ? s_c3[blk - 1] : 0.0;

    double ls = 0.0;
    int R = (int)((n_loc + NTHR - 1) / NTHR);
    for (int r = 0; r < R; r++) {
        int i = r * NTHR + t;
        bool valid = i < (int)n_loc;
        double v2 = valid ? (double)uA.e.e2[i] : 0.0;
        double v3 = valid ? (double)uA.e.e3[i] : 0.0;
#pragma unroll
        for (int o = 1; o < 32; o <<= 1) {
            double u2 = __shfl_up_sync(0xFFFFFFFFu, v2, o);
            double u3 = __shfl_up_sync(0xFFFFFFFFu, v3, o);
            if (lane >= o) { v2 += u2; v3 += u3; }
        }
        if (lane == 31) { s_wt2[warp] = v2; s_wt3[warp] = v3; }
        __syncthreads();
        if (t < 8) {
            double x2 = s_wt2[t], x3 = s_wt3[t];
#pragma unroll
            for (int o = 1; o < 8; o <<= 1) {
                double u2 = __shfl_up_sync(0xFFu, x2, o);
                double u3 = __shfl_up_sync(0xFFu, x3, o);
                if (t >= o) { x2 += u2; x3 += u3; }
            }
            s_wt2[t] = x2; s_wt3[t] = x3;
        }
        __syncthreads();
        if (valid) {
            double incl2 = v2 + (warp ? s_wt2[warp - 1] : 0.0);
            double incl3 = v3 + (warp ? s_wt3[warp - 1] : 0.0);
            ls += (double)logf((float)(carry2 + incl2)) +
                  (double)logf((float)(carry3 + incl3));
        }
        carry2 += s_wt2[7];
        carry3 += s_wt3[7];
        __syncthreads();
    }

#pragma unroll
    for (int o = 16; o > 0; o >>= 1) ls += __shfl_xor_sync(0xFFFFFFFFu, ls, o);
    if (lane == 0) s_wt2[warp] = ls;
    __syncthreads();
    if (t == 0) {
        double s = 0.0;
        for (int j = 0; j < 8; j++) s += s_wt2[j];
        g_part[blk] = s;
    }

    // ---- Final: last block reduces partials, writes out, resets state ------
    if (t == 0) {
        __threadfence();
        amLast = (atomicAdd(&g_done, 1u) == NBLK - 1);
    }
    __syncthreads();
    if (amLast) {
        double p = (t < NBLK) ? __ldcg(&g_part[t]) : 0.0;
#pragma unroll
        for (int o = 16; o > 0; o >>= 1) p += __shfl_xor_sync(0xFFFFFFFFu, p, o);
        __syncthreads();
        if (lane == 0) s_wt2[warp] = p;
        __syncthreads();
        if (t == 0) {
            double s = 0.0;
            for (int j = 0; j < 8; j++) s += s_wt2[j];
            out[0] = (float)((double)N_ROWS * (log(tot2) + log(tot3)) - s);
            g_done = 0u;
            g_bar[0] = 0u;
            g_bar[1] = 0u;
        }
        if (t < NBLK) g_boxcnt[t] = 0u;   // all blocks read it before gbar(1)
    }
}

extern "C" void kernel_launch(void* const* d_in, const int* in_sizes, int n_in,
                              void* d_out, int out_size) {
    const float* o1   = (const float*)d_in[0];  // [65536, 512]
    const float* o2   = (const float*)d_in[1];  // [1, 512]
    const float* o3   = (const float*)d_in[2];  // [1, 512]
    const float* rank = (const float*)d_in[3];  // [65536]
    float* out = (float*)d_out;

    k1_main<<<N_ROWS / 16, 256>>>((const float4*)o1, (const float4*)o2,
                                  (const float4*)o3);
    k2_fused<<<NBLK, NTHR>>>(rank, out);
}